// round 12
// baseline (speedup 1.0000x reference)
#include <cuda_runtime.h>
#include <math.h>
#include <cstdint>

#define NB   2
#define NH   16
#define BH   (NB*NH)
#define SEQ  2048
#define HD   64
#define DM   1024
#define SCALE 0.125f
#define LOG2E 1.4426950408889634f

// ---- scratch (device globals; no allocation APIs allowed) ----
__device__ __align__(16) uint32_t g_qrT_hi[BH*HD*(SEQ/2)];
__device__ __align__(16) uint32_t g_qrT_lo[BH*HD*(SEQ/2)];
__device__ __align__(16) uint32_t g_kT_hi [BH*SEQ*(HD/2)];
__device__ __align__(16) uint32_t g_kT_lo [BH*SEQ*(HD/2)];
__device__ __align__(16) uint32_t g_vt_hi [BH*HD*(SEQ/2)];
__device__ __align__(16) uint32_t g_vt_lo [BH*HD*(SEQ/2)];
__device__ __align__(16) uint32_t g_qs_hi [BH*SEQ*(HD/2)];
__device__ __align__(16) uint32_t g_qs_lo [BH*SEQ*(HD/2)];
__device__ float g_ctx[NB*SEQ*DM];

// ================= split-bf16 helpers =================
__device__ __forceinline__ void split2(float x, float y, uint32_t& hi, uint32_t& lo) {
    uint32_t h;
    asm("cvt.rn.bf16x2.f32 %0, %1, %2;" : "=r"(h) : "f"(y), "f"(x));
    float hx = __uint_as_float(h << 16);
    float hy = __uint_as_float(h & 0xFFFF0000u);
    asm("cvt.rn.bf16x2.f32 %0, %1, %2;" : "=r"(lo) : "f"(y - hy), "f"(x - hx));
    hi = h;
}
__device__ __forceinline__ void split4(float4 a, uint32_t* h2, uint32_t* l2) {
    split2(a.x, a.y, h2[0], l2[0]);
    split2(a.z, a.w, h2[1], l2[1]);
}
__device__ __forceinline__ void mma_bf16(float* c,
        uint32_t a0, uint32_t a1, uint32_t a2, uint32_t a3, uint32_t b0, uint32_t b1) {
    asm volatile("mma.sync.aligned.m16n8k16.row.col.f32.bf16.bf16.f32 "
                 "{%0,%1,%2,%3}, {%4,%5,%6,%7}, {%8,%9}, {%0,%1,%2,%3};"
                 : "+f"(c[0]), "+f"(c[1]), "+f"(c[2]), "+f"(c[3])
                 : "r"(a0), "r"(a1), "r"(a2), "r"(a3), "r"(b0), "r"(b1));
}
__device__ __forceinline__ void mma3(float* c, const uint32_t* ah, const uint32_t* al,
                                     uint32_t bh0, uint32_t bh1, uint32_t bl0, uint32_t bl1) {
    mma_bf16(c, ah[0], ah[1], ah[2], ah[3], bh0, bh1);
    mma_bf16(c, ah[0], ah[1], ah[2], ah[3], bl0, bl1);
    mma_bf16(c, al[0], al[1], al[2], al[3], bh0, bh1);
}

// ================= ldmatrix / cp.async / misc =================
__device__ __forceinline__ void ldsm_x4(uint32_t* r, uint32_t a) {
    asm volatile("ldmatrix.sync.aligned.m8n8.x4.shared.b16 {%0,%1,%2,%3}, [%4];"
                 : "=r"(r[0]), "=r"(r[1]), "=r"(r[2]), "=r"(r[3]) : "r"(a));
}
__device__ __forceinline__ uint32_t smem_to_u32(const void* p) {
    uint32_t a;
    asm("{ .reg .u64 t; cvta.to.shared.u64 t, %1; cvt.u32.u64 %0, t; }" : "=r"(a) : "l"(p));
    return a;
}
__device__ __forceinline__ void cp16(uint32_t saddr, const void* g) {
    asm volatile("cp.async.cg.shared.global [%0], [%1], 16;" :: "r"(saddr), "l"(g));
}
#define CP_COMMIT() asm volatile("cp.async.commit_group;" ::: "memory")
#define CP_WAIT0()  asm volatile("cp.async.wait_group 0;" ::: "memory")
__device__ __forceinline__ float ex2f(float x) {
    float y; asm("ex2.approx.f32 %0, %1;" : "=f"(y) : "f"(x)); return y;
}
__device__ __forceinline__ uint32_t offA(int rb, int stride, int lane) {
    return 4u * ((uint32_t)(rb + (lane & 15)) * stride + ((lane >> 4) & 1) * 4);
}
__device__ __forceinline__ uint32_t offB(int stride, int lane) {
    return 4u * ((uint32_t)((lane & 7) + ((lane >> 4) & 1) * 8) * stride
                 + ((lane >> 3) & 1) * 4);
}

// ============================================================
// 1) RoPE
// ============================================================
__global__ __launch_bounds__(256) void rope_kernel(const float* __restrict__ q,
                                                   const float* __restrict__ k) {
    __shared__ float qs[64][33];
    __shared__ float ks2[32][66];
    int t = threadIdx.x;
    int bh = blockIdx.y;
    int s0 = blockIdx.x * 32;
    int d  = t & 31;
    float inv_freq = 1.0f / powf(10000.0f, (float)(2 * d) * (1.0f / 64.0f));
#pragma unroll
    for (int j = 0; j < 4; j++) {
        int sl = j * 8 + (t >> 5);
        int s = s0 + sl;
        float sn, cs;
        sincosf((float)s * inv_freq, &sn, &cs);
        size_t base = ((size_t)bh * SEQ + s) * HD;
        float a1 = q[base + d], a2 = q[base + d + 32];
        qs[d][sl]      = a1 * cs - a2 * sn;
        qs[d + 32][sl] = a2 * cs + a1 * sn;
        float b1 = k[base + d], b2 = k[base + d + 32];
        ks2[sl][d]      = b1 * cs - b2 * sn;
        ks2[sl][d + 32] = b2 * cs + b1 * sn;
    }
    __syncthreads();
#pragma unroll
    for (int j = 0; j < 4; j++) {
        int idx = j * 256 + t;
        int dd = idx >> 4, sp = idx & 15;
        uint32_t hi, lo;
        split2(qs[dd][2 * sp], qs[dd][2 * sp + 1], hi, lo);
        size_t o = ((size_t)bh * HD + dd) * (SEQ / 2) + s0 / 2 + sp;
        g_qrT_hi[o] = hi; g_qrT_lo[o] = lo;
    }
#pragma unroll
    for (int j = 0; j < 4; j++) {
        int idx = j * 256 + t;
        int sl = idx >> 5, w = idx & 31;
        uint32_t hi, lo;
        split2(ks2[sl][2 * w], ks2[sl][2 * w + 1], hi, lo);
        size_t o = ((size_t)bh * SEQ + s0 + sl) * 32 + w;
        g_kT_hi[o] = hi; g_kT_lo[o] = lo;
    }
}

// ============================================================
// 1b) V transpose
// ============================================================
__global__ __launch_bounds__(256) void vT_kernel(const float* __restrict__ v) {
    __shared__ float vs[64][65];
    int t = threadIdx.x;
    int bh = blockIdx.y;
    int s0 = blockIdx.x * 64;
#pragma unroll
    for (int j = 0; j < 16; j++) {
        int idx = j * 256 + t;
        int sl = idx >> 6, d = idx & 63;
        vs[sl][d] = v[((size_t)bh * SEQ + s0 + sl) * HD + d];
    }
    __syncthreads();
#pragma unroll
    for (int j = 0; j < 8; j++) {
        int idx = j * 256 + t;
        int d = idx >> 5, sp = idx & 31;
        uint32_t hi, lo;
        split2(vs[2 * sp][d], vs[2 * sp + 1][d], hi, lo);
        size_t o = ((size_t)bh * HD + d) * (SEQ / 2) + s0 / 2 + sp;
        g_vt_hi[o] = hi; g_vt_lo[o] = lo;
    }
}

// ============================================================
// 2) qt = W[h] @ qr -- DUAL-BATCH: one CTA = 64 W-rows x both batches.
//    Warps 0-1: b=0, warps 2-3: b=1; A (mask) staged once, shared.
//    Mask HBM traffic halves; per-warp MMA/reg pattern unchanged.
// ============================================================
#define GSTR 20
#define QA_H 0
#define QA_L 1280
#define QB_H 2560      // + batch*1280
#define QB_L 5120      // + batch*1280
#define QBUF 7680
#define QT_SMEM_BYTES (2*QBUF*4)   // 61440

__global__ __launch_bounds__(128) void qt_mma_kernel(const float* __restrict__ mask) {
    extern __shared__ uint32_t qsm[];
    int t = threadIdx.x, w = t >> 5, lane = t & 31;
    int g = lane >> 2, tig = lane & 3;
    int h = blockIdx.y;
    int row0 = blockIdx.x * 64;
    int wb = w >> 1;                 // warp's batch
    int wr = (w & 1) * 32;           // warp's row base within the 64-row A tile
    const float* Ap = mask + (size_t)h * SEQ * SEQ + (size_t)row0 * SEQ;

    uint32_t sb = smem_to_u32(qsm);
    uint32_t oA = offA(wr, GSTR, lane);
    uint32_t oBf = offB(GSTR, lane);

    float acc[2][8][4];
#pragma unroll
    for (int mt = 0; mt < 2; mt++)
#pragma unroll
        for (int nt = 0; nt < 8; nt++)
#pragma unroll
            for (int e = 0; e < 4; e++) acc[mt][nt][e] = 0.f;

    // prefetch chunk 0 into registers
    float4 aR[4]; uint4 bhR[4], blR[4];
#pragma unroll
    for (int j = 0; j < 4; j++) {         // A: 64 rows x 8 float4
        int idx = j * 128 + t;
        int row = idx >> 3, kg = idx & 7;
        aR[j] = *(const float4*)(Ap + (size_t)row * SEQ + kg * 4);
    }
#pragma unroll
    for (int j = 0; j < 4; j++) {         // B: 2 batches x 64 d-rows x 4 uint4
        int bt = j >> 1;
        int rem = ((j & 1) << 7) + t;
        int row = rem >> 2, wq = (rem & 3) * 4;
        size_t o = ((size_t)(bt * NH + h) * HD + row) * (SEQ / 2) + wq;
        bhR[j] = *(const uint4*)&g_qrT_hi[o];
        blR[j] = *(const uint4*)&g_qrT_lo[o];
    }

    const int NC = SEQ / 32;
    for (int c = 0; c < NC; c++) {
        int cur = c & 1;
        uint32_t* Ah = qsm + cur * QBUF + QA_H;
        uint32_t* Al = qsm + cur * QBUF + QA_L;
#pragma unroll
        for (int j = 0; j < 4; j++) {
            int idx = j * 128 + t;
            int row = idx >> 3, kg = idx & 7;
            uint32_t h2[2], l2[2]; split4(aR[j], h2, l2);
            Ah[row * GSTR + kg * 2] = h2[0]; Ah[row * GSTR + kg * 2 + 1] = h2[1];
            Al[row * GSTR + kg * 2] = l2[0]; Al[row * GSTR + kg * 2 + 1] = l2[1];
        }
#pragma unroll
        for (int j = 0; j < 4; j++) {
            int bt = j >> 1;
            int rem = ((j & 1) << 7) + t;
            int row = rem >> 2, wq = (rem & 3) * 4;
            *(uint4*)&qsm[cur * QBUF + QB_H + bt * 1280 + row * GSTR + wq] = bhR[j];
            *(uint4*)&qsm[cur * QBUF + QB_L + bt * 1280 + row * GSTR + wq] = blR[j];
        }
        __syncthreads();
        if (c + 1 < NC) {
            int k0 = (c + 1) * 32;
#pragma unroll
            for (int j = 0; j < 4; j++) {
                int idx = j * 128 + t;
                int row = idx >> 3, kg = idx & 7;
                aR[j] = *(const float4*)(Ap + (size_t)row * SEQ + k0 + kg * 4);
            }
#pragma unroll
            for (int j = 0; j < 4; j++) {
                int bt = j >> 1;
                int rem = ((j & 1) << 7) + t;
                int row = rem >> 2, wq = (rem & 3) * 4;
                size_t o = ((size_t)(bt * NH + h) * HD + row) * (SEQ / 2) + k0 / 2 + wq;
                bhR[j] = *(const uint4*)&g_qrT_hi[o];
                blR[j] = *(const uint4*)&g_qrT_lo[o];
            }
        }
        uint32_t aAh = sb + 4u * (cur * QBUF + QA_H) + oA;
        uint32_t aAl = sb + 4u * (cur * QBUF + QA_L) + oA;
        uint32_t aBh = sb + 4u * (cur * QBUF + QB_H + wb * 1280) + oBf;
        uint32_t aBl = sb + 4u * (cur * QBUF + QB_L + wb * 1280) + oBf;
#pragma unroll
        for (int ks = 0; ks < 2; ks++) {
            uint32_t ah[2][4], al[2][4];
            ldsm_x4(ah[0], aAh + ks * 32);
            ldsm_x4(ah[1], aAh + 16 * GSTR * 4 + ks * 32);
            ldsm_x4(al[0], aAl + ks * 32);
            ldsm_x4(al[1], aAl + 16 * GSTR * 4 + ks * 32);
#pragma unroll
            for (int np = 0; np < 4; np++) {
                uint32_t kh4[4], kl4[4];
                ldsm_x4(kh4, aBh + np * (16 * GSTR * 4) + ks * 32);
                ldsm_x4(kl4, aBl + np * (16 * GSTR * 4) + ks * 32);
                mma3(acc[0][2*np],   ah[0], al[0], kh4[0], kh4[1], kl4[0], kl4[1]);
                mma3(acc[0][2*np+1], ah[0], al[0], kh4[2], kh4[3], kl4[2], kl4[3]);
                mma3(acc[1][2*np],   ah[1], al[1], kh4[0], kh4[1], kl4[0], kl4[1]);
                mma3(acc[1][2*np+1], ah[1], al[1], kh4[2], kh4[3], kl4[2], kl4[3]);
            }
        }
        __syncthreads();
    }
    const float SC = SCALE * LOG2E;
    size_t ro = (size_t)(wb * NH + h) * SEQ + row0 + wr;
#pragma unroll
    for (int mt = 0; mt < 2; mt++)
#pragma unroll
        for (int nt = 0; nt < 8; nt++) {
            uint32_t hi, lo;
            size_t r0 = ro + mt * 16 + g;
            split2(acc[mt][nt][0] * SC, acc[mt][nt][1] * SC, hi, lo);
            g_qs_hi[r0 * 32 + nt * 4 + tig] = hi;
            g_qs_lo[r0 * 32 + nt * 4 + tig] = lo;
            split2(acc[mt][nt][2] * SC, acc[mt][nt][3] * SC, hi, lo);
            g_qs_hi[(r0 + 8) * 32 + nt * 4 + tig] = hi;
            g_qs_lo[(r0 + 8) * 32 + nt * 4 + tig] = lo;
        }
}

// ============================================================
// 3) Flash: 4 warps x 32 q-rows, BN=64, 2 CTAs/SM (champion config)
// ============================================================
#define FSTR 36
#define FQ_H 0
#define FQ_L 4608
#define FKV0 9216
#define KVBUF 9216
#define KH_O 0
#define KL_O 2304
#define VH_O 4608
#define VL_O 6912
#define FLASH_SMEM_BYTES ((FKV0 + 2*KVBUF) * 4)   // 110592

__global__ __launch_bounds__(128, 2) void flash_kernel() {
    extern __shared__ uint32_t fsm[];
    int t = threadIdx.x, w = t >> 5, lane = t & 31;
    int bh = blockIdx.y;
    int b = bh >> 4, h = bh & 15;
    int q0 = blockIdx.x * 128;
    int rb = w * 32;

    uint32_t sb = smem_to_u32(fsm);
    uint32_t oQ  = offA(rb, FSTR, lane);
    uint32_t oBf = offB(FSTR, lane);
    uint32_t aQh = sb + 4u * FQ_H + oQ;
    uint32_t aQl = sb + 4u * FQ_L + oQ;

    const uint32_t* qph = g_qs_hi + ((size_t)bh * SEQ + q0) * 32;
    const uint32_t* qpl = g_qs_lo + ((size_t)bh * SEQ + q0) * 32;
    const uint32_t* kph = g_kT_hi + (size_t)bh * SEQ * 32;
    const uint32_t* kpl = g_kT_lo + (size_t)bh * SEQ * 32;
    const uint32_t* vph = g_vt_hi + (size_t)bh * HD * (SEQ / 2);
    const uint32_t* vpl = g_vt_lo + (size_t)bh * HD * (SEQ / 2);

    {
        uint32_t base = sb + 4u * FKV0;
#pragma unroll
        for (int j = 0; j < 4; j++) {
            int u = j * 128 + t;
            int row = u >> 3, wq = (u & 7) * 4;
            uint32_t so = 4u * (row * FSTR + wq);
            cp16(base + 4u * KH_O + so, kph + (size_t)row * 32 + wq);
            cp16(base + 4u * KL_O + so, kpl + (size_t)row * 32 + wq);
            cp16(base + 4u * VH_O + so, vph + (size_t)row * (SEQ / 2) + wq);
            cp16(base + 4u * VL_O + so, vpl + (size_t)row * (SEQ / 2) + wq);
        }
        CP_COMMIT();
    }
    uint32_t* Qh = fsm + FQ_H;
    uint32_t* Ql = fsm + FQ_L;
#pragma unroll
    for (int j = 0; j < 8; j++) {
        int u = j * 128 + t;
        int row = u >> 3, wq = (u & 7) * 4;
        *(uint4*)&Qh[row * FSTR + wq] = *(const uint4*)&qph[row * 32 + wq];
        *(uint4*)&Ql[row * FSTR + wq] = *(const uint4*)&qpl[row * 32 + wq];
    }

    float m[2][2], l[2][2];
    float ctx[2][8][4];
#pragma unroll
    for (int mt = 0; mt < 2; mt++) {
        m[mt][0] = -1e30f; m[mt][1] = -1e30f;
        l[mt][0] = 0.f;    l[mt][1] = 0.f;
#pragma unroll
        for (int nt = 0; nt < 8; nt++)
#pragma unroll
            for (int e = 0; e < 4; e++) ctx[mt][nt][e] = 0.f;
    }

    const int NT = SEQ / 64;
    for (int kt = 0; kt < NT; kt++) {
        int cur = kt & 1;
        CP_WAIT0();
        __syncthreads();
        if (kt + 1 < NT) {
            uint32_t base = sb + 4u * (FKV0 + (cur ^ 1) * KVBUF);
            int kn = kt + 1;
#pragma unroll
            for (int j = 0; j < 4; j++) {
                int u = j * 128 + t;
                int row = u >> 3, wq = (u & 7) * 4;
                uint32_t so = 4u * (row * FSTR + wq);
                cp16(base + 4u * KH_O + so, kph + (size_t)(kn * 64 + row) * 32 + wq);
                cp16(base + 4u * KL_O + so, kpl + (size_t)(kn * 64 + row) * 32 + wq);
                cp16(base + 4u * VH_O + so, vph + (size_t)row * (SEQ / 2) + kn * 32 + wq);
                cp16(base + 4u * VL_O + so, vpl + (size_t)row * (SEQ / 2) + kn * 32 + wq);
            }
            CP_COMMIT();
        }
        uint32_t kvb = sb + 4u * (FKV0 + cur * KVBUF);
        uint32_t aKh = kvb + 4u * KH_O + oBf;
        uint32_t aKl = kvb + 4u * KL_O + oBf;
        uint32_t aVh = kvb + 4u * VH_O + oBf;
        uint32_t aVl = kvb + 4u * VL_O + oBf;

        float s[2][8][4];
#pragma unroll
        for (int mt = 0; mt < 2; mt++)
#pragma unroll
            for (int nt = 0; nt < 8; nt++)
#pragma unroll
                for (int e = 0; e < 4; e++) s[mt][nt][e] = 0.f;
#pragma unroll
        for (int ks = 0; ks < 4; ks++) {
            uint32_t qh[2][4], ql[2][4];
            ldsm_x4(qh[0], aQh + ks * 32);
            ldsm_x4(ql[0], aQl + ks * 32);
            ldsm_x4(qh[1], aQh + 16 * FSTR * 4 + ks * 32);
            ldsm_x4(ql[1], aQl + 16 * FSTR * 4 + ks * 32);
#pragma unroll
            for (int np = 0; np < 4; np++) {
                uint32_t kh4[4], kl4[4];
                ldsm_x4(kh4, aKh + np * (16 * FSTR * 4) + ks * 32);
                ldsm_x4(kl4, aKl + np * (16 * FSTR * 4) + ks * 32);
                mma3(s[0][2*np],   qh[0], ql[0], kh4[0], kh4[1], kl4[0], kl4[1]);
                mma3(s[0][2*np+1], qh[0], ql[0], kh4[2], kh4[3], kl4[2], kl4[3]);
                mma3(s[1][2*np],   qh[1], ql[1], kh4[0], kh4[1], kl4[0], kl4[1]);
                mma3(s[1][2*np+1], qh[1], ql[1], kh4[2], kh4[3], kl4[2], kl4[3]);
            }
        }

#pragma unroll
        for (int mt = 0; mt < 2; mt++) {
            float rm0 = -1e30f, rm1 = -1e30f;
#pragma unroll
            for (int nt = 0; nt < 8; nt++) {
                rm0 = fmaxf(rm0, fmaxf(s[mt][nt][0], s[mt][nt][1]));
                rm1 = fmaxf(rm1, fmaxf(s[mt][nt][2], s[mt][nt][3]));
            }
            rm0 = fmaxf(rm0, __shfl_xor_sync(0xffffffffu, rm0, 1));
            rm0 = fmaxf(rm0, __shfl_xor_sync(0xffffffffu, rm0, 2));
            rm1 = fmaxf(rm1, __shfl_xor_sync(0xffffffffu, rm1, 1));
            rm1 = fmaxf(rm1, __shfl_xor_sync(0xffffffffu, rm1, 2));
            float mn0 = fmaxf(m[mt][0], rm0), mn1 = fmaxf(m[mt][1], rm1);
            float corr0 = ex2f(m[mt][0] - mn0), corr1 = ex2f(m[mt][1] - mn1);
            m[mt][0] = mn0; m[mt][1] = mn1;
            float rs0 = 0.f, rs1 = 0.f;
#pragma unroll
            for (int nt = 0; nt < 8; nt++) {
                s[mt][nt][0] = ex2f(s[mt][nt][0] - mn0); rs0 += s[mt][nt][0];
                s[mt][nt][1] = ex2f(s[mt][nt][1] - mn0); rs0 += s[mt][nt][1];
                s[mt][nt][2] = ex2f(s[mt][nt][2] - mn1); rs1 += s[mt][nt][2];
                s[mt][nt][3] = ex2f(s[mt][nt][3] - mn1); rs1 += s[mt][nt][3];
            }
            rs0 += __shfl_xor_sync(0xffffffffu, rs0, 1);
            rs0 += __shfl_xor_sync(0xffffffffu, rs0, 2);
            rs1 += __shfl_xor_sync(0xffffffffu, rs1, 1);
            rs1 += __shfl_xor_sync(0xffffffffu, rs1, 2);
            l[mt][0] = l[mt][0] * corr0 + rs0;
            l[mt][1] = l[mt][1] * corr1 + rs1;
#pragma unroll
            for (int nt = 0; nt < 8; nt++) {
                ctx[mt][nt][0] *= corr0; ctx[mt][nt][1] *= corr0;
                ctx[mt][nt][2] *= corr1; ctx[mt][nt][3] *= corr1;
            }
        }

#pragma unroll
        for (int ks = 0; ks < 4; ks++) {
            uint32_t ph[2][4], pl[2][4];
#pragma unroll
            for (int mt = 0; mt < 2; mt++) {
                split2(s[mt][2*ks][0],   s[mt][2*ks][1],   ph[mt][0], pl[mt][0]);
                split2(s[mt][2*ks][2],   s[mt][2*ks][3],   ph[mt][1], pl[mt][1]);
                split2(s[mt][2*ks+1][0], s[mt][2*ks+1][1], ph[mt][2], pl[mt][2]);
                split2(s[mt][2*ks+1][2], s[mt][2*ks+1][3], ph[mt][3], pl[mt][3]);
            }
#pragma unroll
            for (int np = 0; np < 4; np++) {
                uint32_t vh4[4], vl4[4];
                ldsm_x4(vh4, aVh + np * (16 * FSTR * 4) + ks * 32);
                ldsm_x4(vl4, aVl + np * (16 * FSTR * 4) + ks * 32);
                mma3(ctx[0][2*np],   ph[0], pl[0], vh4[0], vh4[1], vl4[0], vl4[1]);
                mma3(ctx[0][2*np+1], ph[0], pl[0], vh4[2], vh4[3], vl4[2], vl4[3]);
                mma3(ctx[1][2*np],   ph[1], pl[1], vh4[0], vh4[1], vl4[0], vl4[1]);
                mma3(ctx[1][2*np+1], ph[1], pl[1], vh4[2], vh4[3], vl4[2], vl4[3]);
            }
        }
    }

    int g = lane >> 2, tig = lane & 3;
#pragma unroll
    for (int mt = 0; mt < 2; mt++) {
        float invl0 = 1.0f / l[mt][0], invl1 = 1.0f / l[mt][1];
        int r0 = q0 + rb + mt * 16 + g;
#pragma unroll
        for (int nt = 0; nt < 8; nt++) {
            int col = h * HD + nt * 8 + 2 * tig;
            *(float2*)(g_ctx + ((size_t)b * SEQ + r0) * DM + col) =
                make_float2(ctx[mt][nt][0] * invl0, ctx[mt][nt][1] * invl0);
            *(float2*)(g_ctx + ((size_t)b * SEQ + r0 + 8) * DM + col) =
                make_float2(ctx[mt][nt][2] * invl1, ctx[mt][nt][3] * invl1);
        }
    }
}

// ============================================================
// 4) out = ctx @ out_w^T + out_b (unchanged; own smem layout macros)
// ============================================================
#define OA_H 0
#define OA_L 2560
#define OB_H 5120
#define OB_L 6400
#define OBUF 7680
#define OUT_SMEM_BYTES (2*OBUF*4)

__global__ __launch_bounds__(128) void out_mma_kernel(const float* __restrict__ wgt,
                                                      const float* __restrict__ bias,
                                                      float* __restrict__ out) {
    extern __shared__ uint32_t qsm[];
    int t = threadIdx.x, w = t >> 5, lane = t & 31;
    int g = lane >> 2, tig = lane & 3;
    int row0 = blockIdx.x * 128;
    int col0 = blockIdx.y * 64;
    const float* Ap = g_ctx + (size_t)row0 * DM;
    const float* Bp = wgt   + (size_t)col0 * DM;

    uint32_t sb = smem_to_u32(qsm);
    uint32_t oA = offA(w * 32, GSTR, lane);
    uint32_t oBf = offB(GSTR, lane);

    float acc[2][8][4];
#pragma unroll
    for (int mt = 0; mt < 2; mt++)
#pragma unroll
        for (int nt = 0; nt < 8; nt++)
#pragma unroll
            for (int e = 0; e < 4; e++) acc[mt][nt][e] = 0.f;

    float4 aR[8], bR[4];
#pragma unroll
    for (int j = 0; j < 8; j++) {
        int idx = j * 128 + t;
        int row = idx >> 3, kg = idx & 7;
        aR[j] = *(const float4*)(Ap + (size_t)row * DM + kg * 4);
    }
#pragma unroll
    for (int j = 0; j < 4; j++) {
        int idx = j * 128 + t;
        int n = idx >> 3, kg = idx & 7;
        bR[j] = *(const float4*)(Bp + (size_t)n * DM + kg * 4);
    }

    const int NC = DM / 32;
    for (int c = 0; c < NC; c++) {
        int cur = c & 1;
        uint32_t* Ah = qsm + cur * OBUF + OA_H;
        uint32_t* Al = qsm + cur * OBUF + OA_L;
        uint32_t* Bh = qsm + cur * OBUF + OB_H;
        uint32_t* Bl = qsm + cur * OBUF + OB_L;
#pragma unroll
        for (int j = 0; j < 8; j++) {
            int idx = j * 128 + t;
            int row = idx >> 3, kg = idx & 7;
            uint32_t h2[2], l2[2]; split4(aR[j], h2, l2);
            Ah[row * GSTR + kg * 2] = h2[0]; Ah[row * GSTR + kg * 2 + 1] = h2[1];
            Al[row * GSTR + kg * 2] = l2[0]; Al[row * GSTR + kg * 2 + 1] = l2[1];
        }
#pragma unroll
        for (int j = 0; j < 4; j++) {
            int idx = j * 128 + t;
            int n = idx >> 3, kg = idx & 7;
            uint32_t h2[2], l2[2]; split4(bR[j], h2, l2);
            Bh[n * GSTR + kg * 2] = h2[0]; Bh[n * GSTR + kg * 2 + 1] = h2[1];
            Bl[n * GSTR + kg * 2] = l2[0]; Bl[n * GSTR + kg * 2 + 1] = l2[1];
        }
        __syncthreads();
        if (c + 1 < NC) {
            int k0 = (c + 1) * 32;
#pragma unroll
            for (int j = 0; j < 8; j++) {
                int idx = j * 128 + t;
                int row = idx >> 3, kg = idx & 7;
                aR[j] = *(const float4*)(Ap + (size_t)row * DM + k0 + kg * 4);
            }
#pragma unroll
            for (int j = 0; j < 4; j++) {
                int idx = j * 128 + t;
                int n = idx >> 3, kg = idx & 7;
                bR[j] = *(const float4*)(Bp + (size_t)n * DM + k0 + kg * 4);
            }
        }
        uint32_t aAh = sb + 4u * (cur * OBUF + OA_H) + oA;
        uint32_t aAl = sb + 4u * (cur * OBUF + OA_L) + oA;
        uint32_t aBh = sb + 4u * (cur * OBUF + OB_H) + oBf;
        uint32_t aBl = sb + 4u * (cur * OBUF + OB_L) + oBf;
#pragma unroll
        for (int ks = 0; ks < 2; ks++) {
            uint32_t ah[2][4], al[2][4];
            ldsm_x4(ah[0], aAh + ks * 32);
            ldsm_x4(ah[1], aAh + 16 * GSTR * 4 + ks * 32);
            ldsm_x4(al[0], aAl + ks * 32);
            ldsm_x4(al[1], aAl + 16 * GSTR * 4 + ks * 32);
#pragma unroll
            for (int np = 0; np < 4; np++) {
                uint32_t kh4[4], kl4[4];
                ldsm_x4(kh4, aBh + np * (16 * GSTR * 4) + ks * 32);
                ldsm_x4(kl4, aBl + np * (16 * GSTR * 4) + ks * 32);
                mma3(acc[0][2*np],   ah[0], al[0], kh4[0], kh4[1], kl4[0], kl4[1]);
                mma3(acc[0][2*np+1], ah[0], al[0], kh4[2], kh4[3], kl4[2], kl4[3]);
                mma3(acc[1][2*np],   ah[1], al[1], kh4[0], kh4[1], kl4[0], kl4[1]);
                mma3(acc[1][2*np+1], ah[1], al[1], kh4[2], kh4[3], kl4[2], kl4[3]);
            }
        }
    }
#pragma unroll
    for (int mt = 0; mt < 2; mt++)
#pragma unroll
        for (int nt = 0; nt < 8; nt++) {
            int col = col0 + nt * 8 + 2 * tig;
            size_t r0 = row0 + w * 32 + mt * 16 + g;
            float2 bi = *(const float2*)(bias + col);
            *(float2*)(out + r0 * DM + col) =
                make_float2(acc[mt][nt][0] + bi.x, acc[mt][nt][1] + bi.y);
            *(float2*)(out + (r0 + 8) * DM + col) =
                make_float2(acc[mt][nt][2] + bi.x, acc[mt][nt][3] + bi.y);
        }
}

// ============================================================
extern "C" void kernel_launch(void* const* d_in, const int* in_sizes, int n_in,
                              void* d_out, int out_size) {
    (void)in_sizes; (void)n_in; (void)out_size;
    const float* q    = (const float*)d_in[0];
    const float* k    = (const float*)d_in[1];
    const float* v    = (const float*)d_in[2];
    const float* mask = (const float*)d_in[3];
    const float* ow   = (const float*)d_in[4];
    const float* ob   = (const float*)d_in[5];
    float* out = (float*)d_out;

    cudaFuncSetAttribute(flash_kernel, cudaFuncAttributeMaxDynamicSharedMemorySize,
                         FLASH_SMEM_BYTES);
    cudaFuncSetAttribute(qt_mma_kernel, cudaFuncAttributeMaxDynamicSharedMemorySize,
                         QT_SMEM_BYTES);
    cudaFuncSetAttribute(out_mma_kernel, cudaFuncAttributeMaxDynamicSharedMemorySize,
                         OUT_SMEM_BYTES);

    rope_kernel<<<dim3(SEQ / 32, BH), 256>>>(q, k);
    vT_kernel<<<dim3(SEQ / 64, BH), 256>>>(v);
    qt_mma_kernel<<<dim3(SEQ / 64, NH), 128, QT_SMEM_BYTES>>>(mask);
    flash_kernel<<<dim3(SEQ / 128, BH), 128, FLASH_SMEM_BYTES>>>();
    out_mma_kernel<<<dim3(NB * SEQ / 128, DM / 64), 128, OUT_SMEM_BYTES>>>(ow, ob, out);
}

// round 13
// speedup vs baseline: 1.0310x; 1.0310x over previous
#include <cuda_runtime.h>
#include <math.h>
#include <cstdint>

#define NB   2
#define NH   16
#define BH   (NB*NH)
#define SEQ  2048
#define HD   64
#define DM   1024
#define SCALE 0.125f
#define LOG2E 1.4426950408889634f

// ---- scratch (device globals; no allocation APIs allowed) ----
__device__ __align__(16) uint32_t g_qrT_hi[BH*HD*(SEQ/2)];
__device__ __align__(16) uint32_t g_qrT_lo[BH*HD*(SEQ/2)];
__device__ __align__(16) uint32_t g_kT_hi [BH*SEQ*(HD/2)];
__device__ __align__(16) uint32_t g_kT_lo [BH*SEQ*(HD/2)];
__device__ __align__(16) uint32_t g_vt_hi [BH*HD*(SEQ/2)];
__device__ __align__(16) uint32_t g_vt_lo [BH*HD*(SEQ/2)];
__device__ __align__(16) uint32_t g_qs_hi [BH*SEQ*(HD/2)];
__device__ __align__(16) uint32_t g_qs_lo [BH*SEQ*(HD/2)];
__device__ __align__(16) uint32_t g_cs_hi [NB*SEQ*(DM/2)];   // pre-split ctx (out A-op)
__device__ __align__(16) uint32_t g_cs_lo [NB*SEQ*(DM/2)];

// ================= split-bf16 helpers =================
__device__ __forceinline__ void split2(float x, float y, uint32_t& hi, uint32_t& lo) {
    uint32_t h;
    asm("cvt.rn.bf16x2.f32 %0, %1, %2;" : "=r"(h) : "f"(y), "f"(x));
    float hx = __uint_as_float(h << 16);
    float hy = __uint_as_float(h & 0xFFFF0000u);
    asm("cvt.rn.bf16x2.f32 %0, %1, %2;" : "=r"(lo) : "f"(y - hy), "f"(x - hx));
    hi = h;
}
__device__ __forceinline__ void split4(float4 a, uint32_t* h2, uint32_t* l2) {
    split2(a.x, a.y, h2[0], l2[0]);
    split2(a.z, a.w, h2[1], l2[1]);
}
__device__ __forceinline__ void mma_bf16(float* c,
        uint32_t a0, uint32_t a1, uint32_t a2, uint32_t a3, uint32_t b0, uint32_t b1) {
    asm volatile("mma.sync.aligned.m16n8k16.row.col.f32.bf16.bf16.f32 "
                 "{%0,%1,%2,%3}, {%4,%5,%6,%7}, {%8,%9}, {%0,%1,%2,%3};"
                 : "+f"(c[0]), "+f"(c[1]), "+f"(c[2]), "+f"(c[3])
                 : "r"(a0), "r"(a1), "r"(a2), "r"(a3), "r"(b0), "r"(b1));
}
__device__ __forceinline__ void mma3(float* c, const uint32_t* ah, const uint32_t* al,
                                     uint32_t bh0, uint32_t bh1, uint32_t bl0, uint32_t bl1) {
    mma_bf16(c, ah[0], ah[1], ah[2], ah[3], bh0, bh1);
    mma_bf16(c, ah[0], ah[1], ah[2], ah[3], bl0, bl1);
    mma_bf16(c, al[0], al[1], al[2], al[3], bh0, bh1);
}

// ================= ldmatrix / cp.async / misc =================
__device__ __forceinline__ void ldsm_x4(uint32_t* r, uint32_t a) {
    asm volatile("ldmatrix.sync.aligned.m8n8.x4.shared.b16 {%0,%1,%2,%3}, [%4];"
                 : "=r"(r[0]), "=r"(r[1]), "=r"(r[2]), "=r"(r[3]) : "r"(a));
}
__device__ __forceinline__ uint32_t smem_to_u32(const void* p) {
    uint32_t a;
    asm("{ .reg .u64 t; cvta.to.shared.u64 t, %1; cvt.u32.u64 %0, t; }" : "=r"(a) : "l"(p));
    return a;
}
__device__ __forceinline__ void cp16(uint32_t saddr, const void* g) {
    asm volatile("cp.async.cg.shared.global [%0], [%1], 16;" :: "r"(saddr), "l"(g));
}
#define CP_COMMIT() asm volatile("cp.async.commit_group;" ::: "memory")
#define CP_WAIT0()  asm volatile("cp.async.wait_group 0;" ::: "memory")
__device__ __forceinline__ float ex2f(float x) {
    float y; asm("ex2.approx.f32 %0, %1;" : "=f"(y) : "f"(x)); return y;
}
__device__ __forceinline__ uint32_t offA(int rb, int stride, int lane) {
    return 4u * ((uint32_t)(rb + (lane & 15)) * stride + ((lane >> 4) & 1) * 4);
}
__device__ __forceinline__ uint32_t offB(int stride, int lane) {
    return 4u * ((uint32_t)((lane & 7) + ((lane >> 4) & 1) * 8) * stride
                 + ((lane >> 3) & 1) * 4);
}

// ============================================================
// 1) RoPE
// ============================================================
__global__ __launch_bounds__(256) void rope_kernel(const float* __restrict__ q,
                                                   const float* __restrict__ k) {
    __shared__ float qs[64][33];
    __shared__ float ks2[32][66];
    int t = threadIdx.x;
    int bh = blockIdx.y;
    int s0 = blockIdx.x * 32;
    int d  = t & 31;
    float inv_freq = 1.0f / powf(10000.0f, (float)(2 * d) * (1.0f / 64.0f));
#pragma unroll
    for (int j = 0; j < 4; j++) {
        int sl = j * 8 + (t >> 5);
        int s = s0 + sl;
        float sn, cs;
        sincosf((float)s * inv_freq, &sn, &cs);
        size_t base = ((size_t)bh * SEQ + s) * HD;
        float a1 = q[base + d], a2 = q[base + d + 32];
        qs[d][sl]      = a1 * cs - a2 * sn;
        qs[d + 32][sl] = a2 * cs + a1 * sn;
        float b1 = k[base + d], b2 = k[base + d + 32];
        ks2[sl][d]      = b1 * cs - b2 * sn;
        ks2[sl][d + 32] = b2 * cs + b1 * sn;
    }
    __syncthreads();
#pragma unroll
    for (int j = 0; j < 4; j++) {
        int idx = j * 256 + t;
        int dd = idx >> 4, sp = idx & 15;
        uint32_t hi, lo;
        split2(qs[dd][2 * sp], qs[dd][2 * sp + 1], hi, lo);
        size_t o = ((size_t)bh * HD + dd) * (SEQ / 2) + s0 / 2 + sp;
        g_qrT_hi[o] = hi; g_qrT_lo[o] = lo;
    }
#pragma unroll
    for (int j = 0; j < 4; j++) {
        int idx = j * 256 + t;
        int sl = idx >> 5, w = idx & 31;
        uint32_t hi, lo;
        split2(ks2[sl][2 * w], ks2[sl][2 * w + 1], hi, lo);
        size_t o = ((size_t)bh * SEQ + s0 + sl) * 32 + w;
        g_kT_hi[o] = hi; g_kT_lo[o] = lo;
    }
}

// ============================================================
// 1b) V transpose
// ============================================================
__global__ __launch_bounds__(256) void vT_kernel(const float* __restrict__ v) {
    __shared__ float vs[64][65];
    int t = threadIdx.x;
    int bh = blockIdx.y;
    int s0 = blockIdx.x * 64;
#pragma unroll
    for (int j = 0; j < 16; j++) {
        int idx = j * 256 + t;
        int sl = idx >> 6, d = idx & 63;
        vs[sl][d] = v[((size_t)bh * SEQ + s0 + sl) * HD + d];
    }
    __syncthreads();
#pragma unroll
    for (int j = 0; j < 8; j++) {
        int idx = j * 256 + t;
        int d = idx >> 5, sp = idx & 31;
        uint32_t hi, lo;
        split2(vs[2 * sp][d], vs[2 * sp + 1][d], hi, lo);
        size_t o = ((size_t)bh * HD + d) * (SEQ / 2) + s0 / 2 + sp;
        g_vt_hi[o] = hi; g_vt_lo[o] = lo;
    }
}

// ============================================================
// 2) qt = W[h] @ qr -- champion: 128-row tile, h-major pairing
// ============================================================
#define GSTR 20
#define QA_H 0
#define QA_L 2560
#define QB_H 5120
#define QB_L 6400
#define QBUF 7680
#define QT_SMEM_BYTES (2*QBUF*4)

__global__ __launch_bounds__(128) void qt_mma_kernel(const float* __restrict__ mask) {
    extern __shared__ uint32_t qsm[];
    int t = threadIdx.x, w = t >> 5, lane = t & 31;
    int g = lane >> 2, tig = lane & 3;
    int yb = blockIdx.y;
    int h = yb >> 1, b = yb & 1;
    int bh = b * NH + h;
    int row0 = blockIdx.x * 128;
    const float* Ap = mask + (size_t)h * SEQ * SEQ + (size_t)row0 * SEQ;
    const uint32_t* Bph = g_qrT_hi + (size_t)bh * HD * (SEQ / 2);
    const uint32_t* Bpl = g_qrT_lo + (size_t)bh * HD * (SEQ / 2);

    uint32_t sb = smem_to_u32(qsm);
    uint32_t oA = offA(w * 32, GSTR, lane);
    uint32_t oBf = offB(GSTR, lane);

    float acc[2][8][4];
#pragma unroll
    for (int mt = 0; mt < 2; mt++)
#pragma unroll
        for (int nt = 0; nt < 8; nt++)
#pragma unroll
            for (int e = 0; e < 4; e++) acc[mt][nt][e] = 0.f;

    float4 aR[8]; uint4 bhR[2], blR[2];
#pragma unroll
    for (int j = 0; j < 8; j++) {
        int idx = j * 128 + t;
        int row = idx >> 3, kg = idx & 7;
        aR[j] = *(const float4*)(Ap + (size_t)row * SEQ + kg * 4);
    }
#pragma unroll
    for (int j = 0; j < 2; j++) {
        int u = j * 128 + t;
        int row = u >> 2, wq = (u & 3) * 4;
        bhR[j] = *(const uint4*)&Bph[(size_t)row * (SEQ / 2) + wq];
        blR[j] = *(const uint4*)&Bpl[(size_t)row * (SEQ / 2) + wq];
    }

    const int NC = SEQ / 32;
    for (int c = 0; c < NC; c++) {
        int cur = c & 1;
        uint32_t* Ah = qsm + cur * QBUF + QA_H;
        uint32_t* Al = qsm + cur * QBUF + QA_L;
        uint32_t* Bh = qsm + cur * QBUF + QB_H;
        uint32_t* Bl = qsm + cur * QBUF + QB_L;
#pragma unroll
        for (int j = 0; j < 8; j++) {
            int idx = j * 128 + t;
            int row = idx >> 3, kg = idx & 7;
            uint32_t h2[2], l2[2]; split4(aR[j], h2, l2);
            Ah[row * GSTR + kg * 2] = h2[0]; Ah[row * GSTR + kg * 2 + 1] = h2[1];
            Al[row * GSTR + kg * 2] = l2[0]; Al[row * GSTR + kg * 2 + 1] = l2[1];
        }
#pragma unroll
        for (int j = 0; j < 2; j++) {
            int u = j * 128 + t;
            int row = u >> 2, wq = (u & 3) * 4;
            *(uint4*)&Bh[row * GSTR + wq] = bhR[j];
            *(uint4*)&Bl[row * GSTR + wq] = blR[j];
        }
        __syncthreads();
        if (c + 1 < NC) {
            int k0 = (c + 1) * 32;
#pragma unroll
            for (int j = 0; j < 8; j++) {
                int idx = j * 128 + t;
                int row = idx >> 3, kg = idx & 7;
                aR[j] = *(const float4*)(Ap + (size_t)row * SEQ + k0 + kg * 4);
            }
#pragma unroll
            for (int j = 0; j < 2; j++) {
                int u = j * 128 + t;
                int row = u >> 2, wq = (u & 3) * 4;
                bhR[j] = *(const uint4*)&Bph[(size_t)row * (SEQ / 2) + k0 / 2 + wq];
                blR[j] = *(const uint4*)&Bpl[(size_t)row * (SEQ / 2) + k0 / 2 + wq];
            }
        }
        uint32_t aAh = sb + 4u * (cur * QBUF + QA_H) + oA;
        uint32_t aAl = sb + 4u * (cur * QBUF + QA_L) + oA;
        uint32_t aBh = sb + 4u * (cur * QBUF + QB_H) + oBf;
        uint32_t aBl = sb + 4u * (cur * QBUF + QB_L) + oBf;
#pragma unroll
        for (int ks = 0; ks < 2; ks++) {
            uint32_t ah[2][4], al[2][4];
            ldsm_x4(ah[0], aAh + ks * 32);
            ldsm_x4(ah[1], aAh + 16 * GSTR * 4 + ks * 32);
            ldsm_x4(al[0], aAl + ks * 32);
            ldsm_x4(al[1], aAl + 16 * GSTR * 4 + ks * 32);
#pragma unroll
            for (int np = 0; np < 4; np++) {
                uint32_t kh4[4], kl4[4];
                ldsm_x4(kh4, aBh + np * (16 * GSTR * 4) + ks * 32);
                ldsm_x4(kl4, aBl + np * (16 * GSTR * 4) + ks * 32);
                mma3(acc[0][2*np],   ah[0], al[0], kh4[0], kh4[1], kl4[0], kl4[1]);
                mma3(acc[0][2*np+1], ah[0], al[0], kh4[2], kh4[3], kl4[2], kl4[3]);
                mma3(acc[1][2*np],   ah[1], al[1], kh4[0], kh4[1], kl4[0], kl4[1]);
                mma3(acc[1][2*np+1], ah[1], al[1], kh4[2], kh4[3], kl4[2], kl4[3]);
            }
        }
    }
    const float SC = SCALE * LOG2E;
    size_t ro = (size_t)bh * SEQ + row0;
#pragma unroll
    for (int mt = 0; mt < 2; mt++)
#pragma unroll
        for (int nt = 0; nt < 8; nt++) {
            uint32_t hi, lo;
            size_t r0 = ro + w * 32 + mt * 16 + g;
            split2(acc[mt][nt][0] * SC, acc[mt][nt][1] * SC, hi, lo);
            g_qs_hi[r0 * 32 + nt * 4 + tig] = hi;
            g_qs_lo[r0 * 32 + nt * 4 + tig] = lo;
            split2(acc[mt][nt][2] * SC, acc[mt][nt][3] * SC, hi, lo);
            g_qs_hi[(r0 + 8) * 32 + nt * 4 + tig] = hi;
            g_qs_lo[(r0 + 8) * 32 + nt * 4 + tig] = lo;
        }
}

// ============================================================
// 3) Flash: 4 warps x 32 q-rows, BN=64, 2 CTAs/SM; epilogue writes
//    PRE-SPLIT ctx pairs (out A-fragment layout)
// ============================================================
#define FSTR 36
#define FQ_H 0
#define FQ_L 4608
#define FKV0 9216
#define KVBUF 9216
#define KH_O 0
#define KL_O 2304
#define VH_O 4608
#define VL_O 6912
#define FLASH_SMEM_BYTES ((FKV0 + 2*KVBUF) * 4)   // 110592

__global__ __launch_bounds__(128, 2) void flash_kernel() {
    extern __shared__ uint32_t fsm[];
    int t = threadIdx.x, w = t >> 5, lane = t & 31;
    int bh = blockIdx.y;
    int b = bh >> 4, h = bh & 15;
    int q0 = blockIdx.x * 128;
    int rb = w * 32;

    uint32_t sb = smem_to_u32(fsm);
    uint32_t oQ  = offA(rb, FSTR, lane);
    uint32_t oBf = offB(FSTR, lane);
    uint32_t aQh = sb + 4u * FQ_H + oQ;
    uint32_t aQl = sb + 4u * FQ_L + oQ;

    const uint32_t* qph = g_qs_hi + ((size_t)bh * SEQ + q0) * 32;
    const uint32_t* qpl = g_qs_lo + ((size_t)bh * SEQ + q0) * 32;
    const uint32_t* kph = g_kT_hi + (size_t)bh * SEQ * 32;
    const uint32_t* kpl = g_kT_lo + (size_t)bh * SEQ * 32;
    const uint32_t* vph = g_vt_hi + (size_t)bh * HD * (SEQ / 2);
    const uint32_t* vpl = g_vt_lo + (size_t)bh * HD * (SEQ / 2);

    {
        uint32_t base = sb + 4u * FKV0;
#pragma unroll
        for (int j = 0; j < 4; j++) {
            int u = j * 128 + t;
            int row = u >> 3, wq = (u & 7) * 4;
            uint32_t so = 4u * (row * FSTR + wq);
            cp16(base + 4u * KH_O + so, kph + (size_t)row * 32 + wq);
            cp16(base + 4u * KL_O + so, kpl + (size_t)row * 32 + wq);
            cp16(base + 4u * VH_O + so, vph + (size_t)row * (SEQ / 2) + wq);
            cp16(base + 4u * VL_O + so, vpl + (size_t)row * (SEQ / 2) + wq);
        }
        CP_COMMIT();
    }
    uint32_t* Qh = fsm + FQ_H;
    uint32_t* Ql = fsm + FQ_L;
#pragma unroll
    for (int j = 0; j < 8; j++) {
        int u = j * 128 + t;
        int row = u >> 3, wq = (u & 7) * 4;
        *(uint4*)&Qh[row * FSTR + wq] = *(const uint4*)&qph[row * 32 + wq];
        *(uint4*)&Ql[row * FSTR + wq] = *(const uint4*)&qpl[row * 32 + wq];
    }

    float m[2][2], l[2][2];
    float ctx[2][8][4];
#pragma unroll
    for (int mt = 0; mt < 2; mt++) {
        m[mt][0] = -1e30f; m[mt][1] = -1e30f;
        l[mt][0] = 0.f;    l[mt][1] = 0.f;
#pragma unroll
        for (int nt = 0; nt < 8; nt++)
#pragma unroll
            for (int e = 0; e < 4; e++) ctx[mt][nt][e] = 0.f;
    }

    const int NT = SEQ / 64;
    for (int kt = 0; kt < NT; kt++) {
        int cur = kt & 1;
        CP_WAIT0();
        __syncthreads();
        if (kt + 1 < NT) {
            uint32_t base = sb + 4u * (FKV0 + (cur ^ 1) * KVBUF);
            int kn = kt + 1;
#pragma unroll
            for (int j = 0; j < 4; j++) {
                int u = j * 128 + t;
                int row = u >> 3, wq = (u & 7) * 4;
                uint32_t so = 4u * (row * FSTR + wq);
                cp16(base + 4u * KH_O + so, kph + (size_t)(kn * 64 + row) * 32 + wq);
                cp16(base + 4u * KL_O + so, kpl + (size_t)(kn * 64 + row) * 32 + wq);
                cp16(base + 4u * VH_O + so, vph + (size_t)row * (SEQ / 2) + kn * 32 + wq);
                cp16(base + 4u * VL_O + so, vpl + (size_t)row * (SEQ / 2) + kn * 32 + wq);
            }
            CP_COMMIT();
        }
        uint32_t kvb = sb + 4u * (FKV0 + cur * KVBUF);
        uint32_t aKh = kvb + 4u * KH_O + oBf;
        uint32_t aKl = kvb + 4u * KL_O + oBf;
        uint32_t aVh = kvb + 4u * VH_O + oBf;
        uint32_t aVl = kvb + 4u * VL_O + oBf;

        float s[2][8][4];
#pragma unroll
        for (int mt = 0; mt < 2; mt++)
#pragma unroll
            for (int nt = 0; nt < 8; nt++)
#pragma unroll
                for (int e = 0; e < 4; e++) s[mt][nt][e] = 0.f;
#pragma unroll
        for (int ks = 0; ks < 4; ks++) {
            uint32_t qh[2][4], ql[2][4];
            ldsm_x4(qh[0], aQh + ks * 32);
            ldsm_x4(ql[0], aQl + ks * 32);
            ldsm_x4(qh[1], aQh + 16 * FSTR * 4 + ks * 32);
            ldsm_x4(ql[1], aQl + 16 * FSTR * 4 + ks * 32);
#pragma unroll
            for (int np = 0; np < 4; np++) {
                uint32_t kh4[4], kl4[4];
                ldsm_x4(kh4, aKh + np * (16 * FSTR * 4) + ks * 32);
                ldsm_x4(kl4, aKl + np * (16 * FSTR * 4) + ks * 32);
                mma3(s[0][2*np],   qh[0], ql[0], kh4[0], kh4[1], kl4[0], kl4[1]);
                mma3(s[0][2*np+1], qh[0], ql[0], kh4[2], kh4[3], kl4[2], kl4[3]);
                mma3(s[1][2*np],   qh[1], ql[1], kh4[0], kh4[1], kl4[0], kl4[1]);
                mma3(s[1][2*np+1], qh[1], ql[1], kh4[2], kh4[3], kl4[2], kl4[3]);
            }
        }

#pragma unroll
        for (int mt = 0; mt < 2; mt++) {
            float rm0 = -1e30f, rm1 = -1e30f;
#pragma unroll
            for (int nt = 0; nt < 8; nt++) {
                rm0 = fmaxf(rm0, fmaxf(s[mt][nt][0], s[mt][nt][1]));
                rm1 = fmaxf(rm1, fmaxf(s[mt][nt][2], s[mt][nt][3]));
            }
            rm0 = fmaxf(rm0, __shfl_xor_sync(0xffffffffu, rm0, 1));
            rm0 = fmaxf(rm0, __shfl_xor_sync(0xffffffffu, rm0, 2));
            rm1 = fmaxf(rm1, __shfl_xor_sync(0xffffffffu, rm1, 1));
            rm1 = fmaxf(rm1, __shfl_xor_sync(0xffffffffu, rm1, 2));
            float mn0 = fmaxf(m[mt][0], rm0), mn1 = fmaxf(m[mt][1], rm1);
            float corr0 = ex2f(m[mt][0] - mn0), corr1 = ex2f(m[mt][1] - mn1);
            m[mt][0] = mn0; m[mt][1] = mn1;
            float rs0 = 0.f, rs1 = 0.f;
#pragma unroll
            for (int nt = 0; nt < 8; nt++) {
                s[mt][nt][0] = ex2f(s[mt][nt][0] - mn0); rs0 += s[mt][nt][0];
                s[mt][nt][1] = ex2f(s[mt][nt][1] - mn0); rs0 += s[mt][nt][1];
                s[mt][nt][2] = ex2f(s[mt][nt][2] - mn1); rs1 += s[mt][nt][2];
                s[mt][nt][3] = ex2f(s[mt][nt][3] - mn1); rs1 += s[mt][nt][3];
            }
            rs0 += __shfl_xor_sync(0xffffffffu, rs0, 1);
            rs0 += __shfl_xor_sync(0xffffffffu, rs0, 2);
            rs1 += __shfl_xor_sync(0xffffffffu, rs1, 1);
            rs1 += __shfl_xor_sync(0xffffffffu, rs1, 2);
            l[mt][0] = l[mt][0] * corr0 + rs0;
            l[mt][1] = l[mt][1] * corr1 + rs1;
#pragma unroll
            for (int nt = 0; nt < 8; nt++) {
                ctx[mt][nt][0] *= corr0; ctx[mt][nt][1] *= corr0;
                ctx[mt][nt][2] *= corr1; ctx[mt][nt][3] *= corr1;
            }
        }

#pragma unroll
        for (int ks = 0; ks < 4; ks++) {
            uint32_t ph[2][4], pl[2][4];
#pragma unroll
            for (int mt = 0; mt < 2; mt++) {
                split2(s[mt][2*ks][0],   s[mt][2*ks][1],   ph[mt][0], pl[mt][0]);
                split2(s[mt][2*ks][2],   s[mt][2*ks][3],   ph[mt][1], pl[mt][1]);
                split2(s[mt][2*ks+1][0], s[mt][2*ks+1][1], ph[mt][2], pl[mt][2]);
                split2(s[mt][2*ks+1][2], s[mt][2*ks+1][3], ph[mt][3], pl[mt][3]);
            }
#pragma unroll
            for (int np = 0; np < 4; np++) {
                uint32_t vh4[4], vl4[4];
                ldsm_x4(vh4, aVh + np * (16 * FSTR * 4) + ks * 32);
                ldsm_x4(vl4, aVl + np * (16 * FSTR * 4) + ks * 32);
                mma3(ctx[0][2*np],   ph[0], pl[0], vh4[0], vh4[1], vl4[0], vl4[1]);
                mma3(ctx[0][2*np+1], ph[0], pl[0], vh4[2], vh4[3], vl4[2], vl4[3]);
                mma3(ctx[1][2*np],   ph[1], pl[1], vh4[0], vh4[1], vl4[0], vl4[1]);
                mma3(ctx[1][2*np+1], ph[1], pl[1], vh4[2], vh4[3], vl4[2], vl4[3]);
            }
        }
    }

    // Epilogue: normalize, split, store pre-split ctx pairs (out A layout).
    // Pair-word index within row = (h*64 + nt*8 + 2*tig)/2 = h*32 + nt*4 + tig.
    int g = lane >> 2, tig = lane & 3;
#pragma unroll
    for (int mt = 0; mt < 2; mt++) {
        float invl0 = 1.0f / l[mt][0], invl1 = 1.0f / l[mt][1];
        size_t r0 = (size_t)b * SEQ + q0 + rb + mt * 16 + g;
#pragma unroll
        for (int nt = 0; nt < 8; nt++) {
            int pw = h * 32 + nt * 4 + tig;
            uint32_t hi, lo;
            split2(ctx[mt][nt][0] * invl0, ctx[mt][nt][1] * invl0, hi, lo);
            g_cs_hi[r0 * (DM / 2) + pw] = hi;
            g_cs_lo[r0 * (DM / 2) + pw] = lo;
            split2(ctx[mt][nt][2] * invl1, ctx[mt][nt][3] * invl1, hi, lo);
            g_cs_hi[(r0 + 8) * (DM / 2) + pw] = hi;
            g_cs_lo[(r0 + 8) * (DM / 2) + pw] = lo;
        }
    }
}

// ============================================================
// 4) out = ctx @ out_w^T + out_b -- A from pre-split ctx (pure copies)
// ============================================================
#define OA_H 0
#define OA_L 2560
#define OB_H 5120
#define OB_L 6400
#define OBUF 7680
#define OUT_SMEM_BYTES (2*OBUF*4)

__global__ __launch_bounds__(128) void out_mma_kernel(const float* __restrict__ wgt,
                                                      const float* __restrict__ bias,
                                                      float* __restrict__ out) {
    extern __shared__ uint32_t qsm[];
    int t = threadIdx.x, w = t >> 5, lane = t & 31;
    int g = lane >> 2, tig = lane & 3;
    int row0 = blockIdx.x * 128;
    int col0 = blockIdx.y * 64;
    const uint32_t* Aph = g_cs_hi + (size_t)row0 * (DM / 2);
    const uint32_t* Apl = g_cs_lo + (size_t)row0 * (DM / 2);
    const float* Bp = wgt + (size_t)col0 * DM;

    uint32_t sb = smem_to_u32(qsm);
    uint32_t oA = offA(w * 32, GSTR, lane);
    uint32_t oBf = offB(GSTR, lane);

    float acc[2][8][4];
#pragma unroll
    for (int mt = 0; mt < 2; mt++)
#pragma unroll
        for (int nt = 0; nt < 8; nt++)
#pragma unroll
            for (int e = 0; e < 4; e++) acc[mt][nt][e] = 0.f;

    uint4 ahR[4], alR[4]; float4 bR[4];
#pragma unroll
    for (int j = 0; j < 4; j++) {           // A: 128 rows x 16 pair-words (hi+lo)
        int u = j * 128 + t;
        int row = u >> 2, wq = (u & 3) * 4;
        ahR[j] = *(const uint4*)&Aph[(size_t)row * (DM / 2) + wq];
        alR[j] = *(const uint4*)&Apl[(size_t)row * (DM / 2) + wq];
    }
#pragma unroll
    for (int j = 0; j < 4; j++) {
        int idx = j * 128 + t;
        int n = idx >> 3, kg = idx & 7;
        bR[j] = *(const float4*)(Bp + (size_t)n * DM + kg * 4);
    }

    const int NC = DM / 32;
    for (int c = 0; c < NC; c++) {
        int cur = c & 1;
        uint32_t* Ah = qsm + cur * OBUF + OA_H;
        uint32_t* Al = qsm + cur * OBUF + OA_L;
        uint32_t* Bh = qsm + cur * OBUF + OB_H;
        uint32_t* Bl = qsm + cur * OBUF + OB_L;
#pragma unroll
        for (int j = 0; j < 4; j++) {       // A: pure word copies
            int u = j * 128 + t;
            int row = u >> 2, wq = (u & 3) * 4;
            *(uint4*)&Ah[row * GSTR + wq] = ahR[j];
            *(uint4*)&Al[row * GSTR + wq] = alR[j];
        }
#pragma unroll
        for (int j = 0; j < 4; j++) {
            int idx = j * 128 + t;
            int n = idx >> 3, kg = idx & 7;
            uint32_t h2[2], l2[2]; split4(bR[j], h2, l2);
            Bh[n * GSTR + kg * 2] = h2[0]; Bh[n * GSTR + kg * 2 + 1] = h2[1];
            Bl[n * GSTR + kg * 2] = l2[0]; Bl[n * GSTR + kg * 2 + 1] = l2[1];
        }
        __syncthreads();
        if (c + 1 < NC) {
            int kw = (c + 1) * 16;          // pair-word offset
            int k0 = (c + 1) * 32;
#pragma unroll
            for (int j = 0; j < 4; j++) {
                int u = j * 128 + t;
                int row = u >> 2, wq = (u & 3) * 4;
                ahR[j] = *(const uint4*)&Aph[(size_t)row * (DM / 2) + kw + wq];
                alR[j] = *(const uint4*)&Apl[(size_t)row * (DM / 2) + kw + wq];
            }
#pragma unroll
            for (int j = 0; j < 4; j++) {
                int idx = j * 128 + t;
                int n = idx >> 3, kg = idx & 7;
                bR[j] = *(const float4*)(Bp + (size_t)n * DM + k0 + kg * 4);
            }
        }
        uint32_t aAh = sb + 4u * (cur * OBUF + OA_H) + oA;
        uint32_t aAl = sb + 4u * (cur * OBUF + OA_L) + oA;
        uint32_t aBh = sb + 4u * (cur * OBUF + OB_H) + oBf;
        uint32_t aBl = sb + 4u * (cur * OBUF + OB_L) + oBf;
#pragma unroll
        for (int ks = 0; ks < 2; ks++) {
            uint32_t ah[2][4], al[2][4];
            ldsm_x4(ah[0], aAh + ks * 32);
            ldsm_x4(ah[1], aAh + 16 * GSTR * 4 + ks * 32);
            ldsm_x4(al[0], aAl + ks * 32);
            ldsm_x4(al[1], aAl + 16 * GSTR * 4 + ks * 32);
#pragma unroll
            for (int np = 0; np < 4; np++) {
                uint32_t kh4[4], kl4[4];
                ldsm_x4(kh4, aBh + np * (16 * GSTR * 4) + ks * 32);
                ldsm_x4(kl4, aBl + np * (16 * GSTR * 4) + ks * 32);
                mma3(acc[0][2*np],   ah[0], al[0], kh4[0], kh4[1], kl4[0], kl4[1]);
                mma3(acc[0][2*np+1], ah[0], al[0], kh4[2], kh4[3], kl4[2], kl4[3]);
                mma3(acc[1][2*np],   ah[1], al[1], kh4[0], kh4[1], kl4[0], kl4[1]);
                mma3(acc[1][2*np+1], ah[1], al[1], kh4[2], kh4[3], kl4[2], kl4[3]);
            }
        }
    }
#pragma unroll
    for (int mt = 0; mt < 2; mt++)
#pragma unroll
        for (int nt = 0; nt < 8; nt++) {
            int col = col0 + nt * 8 + 2 * tig;
            size_t r0 = row0 + w * 32 + mt * 16 + g;
            float2 bi = *(const float2*)(bias + col);
            *(float2*)(out + r0 * DM + col) =
                make_float2(acc[mt][nt][0] + bi.x, acc[mt][nt][1] + bi.y);
            *(float2*)(out + (r0 + 8) * DM + col) =
                make_float2(acc[mt][nt][2] + bi.x, acc[mt][nt][3] + bi.y);
        }
}

// ============================================================
extern "C" void kernel_launch(void* const* d_in, const int* in_sizes, int n_in,
                              void* d_out, int out_size) {
    (void)in_sizes; (void)n_in; (void)out_size;
    const float* q    = (const float*)d_in[0];
    const float* k    = (const float*)d_in[1];
    const float* v    = (const float*)d_in[2];
    const float* mask = (const float*)d_in[3];
    const float* ow   = (const float*)d_in[4];
    const float* ob   = (const float*)d_in[5];
    float* out = (float*)d_out;

    cudaFuncSetAttribute(flash_kernel, cudaFuncAttributeMaxDynamicSharedMemorySize,
                         FLASH_SMEM_BYTES);
    cudaFuncSetAttribute(qt_mma_kernel, cudaFuncAttributeMaxDynamicSharedMemorySize,
                         QT_SMEM_BYTES);
    cudaFuncSetAttribute(out_mma_kernel, cudaFuncAttributeMaxDynamicSharedMemorySize,
                         OUT_SMEM_BYTES);

    rope_kernel<<<dim3(SEQ / 32, BH), 256>>>(q, k);
    vT_kernel<<<dim3(SEQ / 64, BH), 256>>>(v);
    qt_mma_kernel<<<dim3(SEQ / 128, BH), 128, QT_SMEM_BYTES>>>(mask);
    flash_kernel<<<dim3(SEQ / 128, BH), 128, FLASH_SMEM_BYTES>>>();
    out_mma_kernel<<<dim3(NB * SEQ / 128, DM / 64), 128, OUT_SMEM_BYTES>>>(ow, ob, out);
}

// round 14
// speedup vs baseline: 1.0529x; 1.0212x over previous
#include <cuda_runtime.h>
#include <math.h>
#include <cstdint>

#define NB   2
#define NH   16
#define BH   (NB*NH)
#define SEQ  2048
#define HD   64
#define DM   1024
#define SCALE 0.125f
#define LOG2E 1.4426950408889634f

// ---- scratch (device globals; no allocation APIs allowed) ----
__device__ __align__(16) uint32_t g_qrT_hi[BH*HD*(SEQ/2)];
__device__ __align__(16) uint32_t g_qrT_lo[BH*HD*(SEQ/2)];
__device__ __align__(16) uint32_t g_kT_hi [BH*SEQ*(HD/2)];
__device__ __align__(16) uint32_t g_kT_lo [BH*SEQ*(HD/2)];
__device__ __align__(16) uint32_t g_vt_hi [BH*HD*(SEQ/2)];
__device__ __align__(16) uint32_t g_vt_lo [BH*HD*(SEQ/2)];
__device__ __align__(16) uint32_t g_qs_hi [BH*SEQ*(HD/2)];
__device__ __align__(16) uint32_t g_qs_lo [BH*SEQ*(HD/2)];
__device__ float g_ctx[NB*SEQ*DM];

// ================= split-bf16 helpers =================
__device__ __forceinline__ void split2(float x, float y, uint32_t& hi, uint32_t& lo) {
    uint32_t h;
    asm("cvt.rn.bf16x2.f32 %0, %1, %2;" : "=r"(h) : "f"(y), "f"(x));
    float hx = __uint_as_float(h << 16);
    float hy = __uint_as_float(h & 0xFFFF0000u);
    asm("cvt.rn.bf16x2.f32 %0, %1, %2;" : "=r"(lo) : "f"(y - hy), "f"(x - hx));
    hi = h;
}
__device__ __forceinline__ void split4(float4 a, uint32_t* h2, uint32_t* l2) {
    split2(a.x, a.y, h2[0], l2[0]);
    split2(a.z, a.w, h2[1], l2[1]);
}
__device__ __forceinline__ void mma_bf16(float* c,
        uint32_t a0, uint32_t a1, uint32_t a2, uint32_t a3, uint32_t b0, uint32_t b1) {
    asm volatile("mma.sync.aligned.m16n8k16.row.col.f32.bf16.bf16.f32 "
                 "{%0,%1,%2,%3}, {%4,%5,%6,%7}, {%8,%9}, {%0,%1,%2,%3};"
                 : "+f"(c[0]), "+f"(c[1]), "+f"(c[2]), "+f"(c[3])
                 : "r"(a0), "r"(a1), "r"(a2), "r"(a3), "r"(b0), "r"(b1));
}
__device__ __forceinline__ void mma3(float* c, const uint32_t* ah, const uint32_t* al,
                                     uint32_t bh0, uint32_t bh1, uint32_t bl0, uint32_t bl1) {
    mma_bf16(c, ah[0], ah[1], ah[2], ah[3], bh0, bh1);
    mma_bf16(c, ah[0], ah[1], ah[2], ah[3], bl0, bl1);
    mma_bf16(c, al[0], al[1], al[2], al[3], bh0, bh1);
}

// ================= ldmatrix / cp.async / misc =================
__device__ __forceinline__ void ldsm_x4(uint32_t* r, uint32_t a) {
    asm volatile("ldmatrix.sync.aligned.m8n8.x4.shared.b16 {%0,%1,%2,%3}, [%4];"
                 : "=r"(r[0]), "=r"(r[1]), "=r"(r[2]), "=r"(r[3]) : "r"(a));
}
__device__ __forceinline__ uint32_t smem_to_u32(const void* p) {
    uint32_t a;
    asm("{ .reg .u64 t; cvta.to.shared.u64 t, %1; cvt.u32.u64 %0, t; }" : "=r"(a) : "l"(p));
    return a;
}
__device__ __forceinline__ void cp16(uint32_t saddr, const void* g) {
    asm volatile("cp.async.cg.shared.global [%0], [%1], 16;" :: "r"(saddr), "l"(g));
}
#define CP_COMMIT() asm volatile("cp.async.commit_group;" ::: "memory")
#define CP_WAIT0()  asm volatile("cp.async.wait_group 0;" ::: "memory")
__device__ __forceinline__ float ex2f(float x) {
    float y; asm("ex2.approx.f32 %0, %1;" : "=f"(y) : "f"(x)); return y;
}
__device__ __forceinline__ uint32_t offA(int rb, int stride, int lane) {
    return 4u * ((uint32_t)(rb + (lane & 15)) * stride + ((lane >> 4) & 1) * 4);
}
__device__ __forceinline__ uint32_t offB(int stride, int lane) {
    return 4u * ((uint32_t)((lane & 7) + ((lane >> 4) & 1) * 8) * stride
                 + ((lane >> 3) & 1) * 4);
}

// ============================================================
// 1) Fused RoPE + V transpose: one block = 32 seq rows of one (b,h).
//    q -> g_qrT (pairs along seq), k -> g_kT (pairs along d),
//    v -> g_vt (pairs along seq), all split-bf16.
// ============================================================
__global__ __launch_bounds__(256) void rope_v_kernel(const float* __restrict__ q,
                                                     const float* __restrict__ k,
                                                     const float* __restrict__ v) {
    __shared__ float qs[64][33];
    __shared__ float ks2[32][66];
    __shared__ float vs[32][66];
    int t = threadIdx.x;
    int bh = blockIdx.y;
    int s0 = blockIdx.x * 32;
    int d  = t & 31;
    float inv_freq = 1.0f / powf(10000.0f, (float)(2 * d) * (1.0f / 64.0f));
#pragma unroll
    for (int j = 0; j < 4; j++) {
        int sl = j * 8 + (t >> 5);
        int s = s0 + sl;
        float sn, cs;
        sincosf((float)s * inv_freq, &sn, &cs);
        size_t base = ((size_t)bh * SEQ + s) * HD;
        float a1 = q[base + d], a2 = q[base + d + 32];
        qs[d][sl]      = a1 * cs - a2 * sn;
        qs[d + 32][sl] = a2 * cs + a1 * sn;
        float b1 = k[base + d], b2 = k[base + d + 32];
        ks2[sl][d]      = b1 * cs - b2 * sn;
        ks2[sl][d + 32] = b2 * cs + b1 * sn;
    }
    // V: 32 rows x 64 d, plain load into smem (overlaps rope math above)
#pragma unroll
    for (int j = 0; j < 8; j++) {
        int idx = j * 256 + t;
        int sl = idx >> 6, dd = idx & 63;
        vs[sl][dd] = v[((size_t)bh * SEQ + s0 + sl) * HD + dd];
    }
    __syncthreads();
#pragma unroll
    for (int j = 0; j < 4; j++) {     // q out: [d][seq-pair]
        int idx = j * 256 + t;
        int dd = idx >> 4, sp = idx & 15;
        uint32_t hi, lo;
        split2(qs[dd][2 * sp], qs[dd][2 * sp + 1], hi, lo);
        size_t o = ((size_t)bh * HD + dd) * (SEQ / 2) + s0 / 2 + sp;
        g_qrT_hi[o] = hi; g_qrT_lo[o] = lo;
    }
#pragma unroll
    for (int j = 0; j < 4; j++) {     // k out: [key][d-pair]
        int idx = j * 256 + t;
        int sl = idx >> 5, w = idx & 31;
        uint32_t hi, lo;
        split2(ks2[sl][2 * w], ks2[sl][2 * w + 1], hi, lo);
        size_t o = ((size_t)bh * SEQ + s0 + sl) * 32 + w;
        g_kT_hi[o] = hi; g_kT_lo[o] = lo;
    }
#pragma unroll
    for (int j = 0; j < 4; j++) {     // v out: [d][seq-pair]
        int idx = j * 256 + t;
        int dd = idx >> 4, sp = idx & 15;
        uint32_t hi, lo;
        split2(vs[2 * sp][dd], vs[2 * sp + 1][dd], hi, lo);
        size_t o = ((size_t)bh * HD + dd) * (SEQ / 2) + s0 / 2 + sp;
        g_vt_hi[o] = hi; g_vt_lo[o] = lo;
    }
}

// ============================================================
// 2) qt = W[h] @ qr -- champion: 128-row tile, h-major pairing
// ============================================================
#define GSTR 20
#define QA_H 0
#define QA_L 2560
#define QB_H 5120
#define QB_L 6400
#define QBUF 7680
#define QT_SMEM_BYTES (2*QBUF*4)

__global__ __launch_bounds__(128) void qt_mma_kernel(const float* __restrict__ mask) {
    extern __shared__ uint32_t qsm[];
    int t = threadIdx.x, w = t >> 5, lane = t & 31;
    int g = lane >> 2, tig = lane & 3;
    int yb = blockIdx.y;
    int h = yb >> 1, b = yb & 1;
    int bh = b * NH + h;
    int row0 = blockIdx.x * 128;
    const float* Ap = mask + (size_t)h * SEQ * SEQ + (size_t)row0 * SEQ;
    const uint32_t* Bph = g_qrT_hi + (size_t)bh * HD * (SEQ / 2);
    const uint32_t* Bpl = g_qrT_lo + (size_t)bh * HD * (SEQ / 2);

    uint32_t sb = smem_to_u32(qsm);
    uint32_t oA = offA(w * 32, GSTR, lane);
    uint32_t oBf = offB(GSTR, lane);

    float acc[2][8][4];
#pragma unroll
    for (int mt = 0; mt < 2; mt++)
#pragma unroll
        for (int nt = 0; nt < 8; nt++)
#pragma unroll
            for (int e = 0; e < 4; e++) acc[mt][nt][e] = 0.f;

    float4 aR[8]; uint4 bhR[2], blR[2];
#pragma unroll
    for (int j = 0; j < 8; j++) {
        int idx = j * 128 + t;
        int row = idx >> 3, kg = idx & 7;
        aR[j] = *(const float4*)(Ap + (size_t)row * SEQ + kg * 4);
    }
#pragma unroll
    for (int j = 0; j < 2; j++) {
        int u = j * 128 + t;
        int row = u >> 2, wq = (u & 3) * 4;
        bhR[j] = *(const uint4*)&Bph[(size_t)row * (SEQ / 2) + wq];
        blR[j] = *(const uint4*)&Bpl[(size_t)row * (SEQ / 2) + wq];
    }

    const int NC = SEQ / 32;
    for (int c = 0; c < NC; c++) {
        int cur = c & 1;
        uint32_t* Ah = qsm + cur * QBUF + QA_H;
        uint32_t* Al = qsm + cur * QBUF + QA_L;
        uint32_t* Bh = qsm + cur * QBUF + QB_H;
        uint32_t* Bl = qsm + cur * QBUF + QB_L;
#pragma unroll
        for (int j = 0; j < 8; j++) {
            int idx = j * 128 + t;
            int row = idx >> 3, kg = idx & 7;
            uint32_t h2[2], l2[2]; split4(aR[j], h2, l2);
            Ah[row * GSTR + kg * 2] = h2[0]; Ah[row * GSTR + kg * 2 + 1] = h2[1];
            Al[row * GSTR + kg * 2] = l2[0]; Al[row * GSTR + kg * 2 + 1] = l2[1];
        }
#pragma unroll
        for (int j = 0; j < 2; j++) {
            int u = j * 128 + t;
            int row = u >> 2, wq = (u & 3) * 4;
            *(uint4*)&Bh[row * GSTR + wq] = bhR[j];
            *(uint4*)&Bl[row * GSTR + wq] = blR[j];
        }
        __syncthreads();
        if (c + 1 < NC) {
            int k0 = (c + 1) * 32;
#pragma unroll
            for (int j = 0; j < 8; j++) {
                int idx = j * 128 + t;
                int row = idx >> 3, kg = idx & 7;
                aR[j] = *(const float4*)(Ap + (size_t)row * SEQ + k0 + kg * 4);
            }
#pragma unroll
            for (int j = 0; j < 2; j++) {
                int u = j * 128 + t;
                int row = u >> 2, wq = (u & 3) * 4;
                bhR[j] = *(const uint4*)&Bph[(size_t)row * (SEQ / 2) + k0 / 2 + wq];
                blR[j] = *(const uint4*)&Bpl[(size_t)row * (SEQ / 2) + k0 / 2 + wq];
            }
        }
        uint32_t aAh = sb + 4u * (cur * QBUF + QA_H) + oA;
        uint32_t aAl = sb + 4u * (cur * QBUF + QA_L) + oA;
        uint32_t aBh = sb + 4u * (cur * QBUF + QB_H) + oBf;
        uint32_t aBl = sb + 4u * (cur * QBUF + QB_L) + oBf;
#pragma unroll
        for (int ks = 0; ks < 2; ks++) {
            uint32_t ah[2][4], al[2][4];
            ldsm_x4(ah[0], aAh + ks * 32);
            ldsm_x4(ah[1], aAh + 16 * GSTR * 4 + ks * 32);
            ldsm_x4(al[0], aAl + ks * 32);
            ldsm_x4(al[1], aAl + 16 * GSTR * 4 + ks * 32);
#pragma unroll
            for (int np = 0; np < 4; np++) {
                uint32_t kh4[4], kl4[4];
                ldsm_x4(kh4, aBh + np * (16 * GSTR * 4) + ks * 32);
                ldsm_x4(kl4, aBl + np * (16 * GSTR * 4) + ks * 32);
                mma3(acc[0][2*np],   ah[0], al[0], kh4[0], kh4[1], kl4[0], kl4[1]);
                mma3(acc[0][2*np+1], ah[0], al[0], kh4[2], kh4[3], kl4[2], kl4[3]);
                mma3(acc[1][2*np],   ah[1], al[1], kh4[0], kh4[1], kl4[0], kl4[1]);
                mma3(acc[1][2*np+1], ah[1], al[1], kh4[2], kh4[3], kl4[2], kl4[3]);
            }
        }
    }
    const float SC = SCALE * LOG2E;
    size_t ro = (size_t)bh * SEQ + row0;
#pragma unroll
    for (int mt = 0; mt < 2; mt++)
#pragma unroll
        for (int nt = 0; nt < 8; nt++) {
            uint32_t hi, lo;
            size_t r0 = ro + w * 32 + mt * 16 + g;
            split2(acc[mt][nt][0] * SC, acc[mt][nt][1] * SC, hi, lo);
            g_qs_hi[r0 * 32 + nt * 4 + tig] = hi;
            g_qs_lo[r0 * 32 + nt * 4 + tig] = lo;
            split2(acc[mt][nt][2] * SC, acc[mt][nt][3] * SC, hi, lo);
            g_qs_hi[(r0 + 8) * 32 + nt * 4 + tig] = hi;
            g_qs_lo[(r0 + 8) * 32 + nt * 4 + tig] = lo;
        }
}

// ============================================================
// 3) Flash: 4 warps x 32 q-rows, BN=64, 2 CTAs/SM (champion)
// ============================================================
#define FSTR 36
#define FQ_H 0
#define FQ_L 4608
#define FKV0 9216
#define KVBUF 9216
#define KH_O 0
#define KL_O 2304
#define VH_O 4608
#define VL_O 6912
#define FLASH_SMEM_BYTES ((FKV0 + 2*KVBUF) * 4)   // 110592

__global__ __launch_bounds__(128, 2) void flash_kernel() {
    extern __shared__ uint32_t fsm[];
    int t = threadIdx.x, w = t >> 5, lane = t & 31;
    int bh = blockIdx.y;
    int b = bh >> 4, h = bh & 15;
    int q0 = blockIdx.x * 128;
    int rb = w * 32;

    uint32_t sb = smem_to_u32(fsm);
    uint32_t oQ  = offA(rb, FSTR, lane);
    uint32_t oBf = offB(FSTR, lane);
    uint32_t aQh = sb + 4u * FQ_H + oQ;
    uint32_t aQl = sb + 4u * FQ_L + oQ;

    const uint32_t* qph = g_qs_hi + ((size_t)bh * SEQ + q0) * 32;
    const uint32_t* qpl = g_qs_lo + ((size_t)bh * SEQ + q0) * 32;
    const uint32_t* kph = g_kT_hi + (size_t)bh * SEQ * 32;
    const uint32_t* kpl = g_kT_lo + (size_t)bh * SEQ * 32;
    const uint32_t* vph = g_vt_hi + (size_t)bh * HD * (SEQ / 2);
    const uint32_t* vpl = g_vt_lo + (size_t)bh * HD * (SEQ / 2);

    {
        uint32_t base = sb + 4u * FKV0;
#pragma unroll
        for (int j = 0; j < 4; j++) {
            int u = j * 128 + t;
            int row = u >> 3, wq = (u & 7) * 4;
            uint32_t so = 4u * (row * FSTR + wq);
            cp16(base + 4u * KH_O + so, kph + (size_t)row * 32 + wq);
            cp16(base + 4u * KL_O + so, kpl + (size_t)row * 32 + wq);
            cp16(base + 4u * VH_O + so, vph + (size_t)row * (SEQ / 2) + wq);
            cp16(base + 4u * VL_O + so, vpl + (size_t)row * (SEQ / 2) + wq);
        }
        CP_COMMIT();
    }
    uint32_t* Qh = fsm + FQ_H;
    uint32_t* Ql = fsm + FQ_L;
#pragma unroll
    for (int j = 0; j < 8; j++) {
        int u = j * 128 + t;
        int row = u >> 3, wq = (u & 7) * 4;
        *(uint4*)&Qh[row * FSTR + wq] = *(const uint4*)&qph[row * 32 + wq];
        *(uint4*)&Ql[row * FSTR + wq] = *(const uint4*)&qpl[row * 32 + wq];
    }

    float m[2][2], l[2][2];
    float ctx[2][8][4];
#pragma unroll
    for (int mt = 0; mt < 2; mt++) {
        m[mt][0] = -1e30f; m[mt][1] = -1e30f;
        l[mt][0] = 0.f;    l[mt][1] = 0.f;
#pragma unroll
        for (int nt = 0; nt < 8; nt++)
#pragma unroll
            for (int e = 0; e < 4; e++) ctx[mt][nt][e] = 0.f;
    }

    const int NT = SEQ / 64;
    for (int kt = 0; kt < NT; kt++) {
        int cur = kt & 1;
        CP_WAIT0();
        __syncthreads();
        if (kt + 1 < NT) {
            uint32_t base = sb + 4u * (FKV0 + (cur ^ 1) * KVBUF);
            int kn = kt + 1;
#pragma unroll
            for (int j = 0; j < 4; j++) {
                int u = j * 128 + t;
                int row = u >> 3, wq = (u & 7) * 4;
                uint32_t so = 4u * (row * FSTR + wq);
                cp16(base + 4u * KH_O + so, kph + (size_t)(kn * 64 + row) * 32 + wq);
                cp16(base + 4u * KL_O + so, kpl + (size_t)(kn * 64 + row) * 32 + wq);
                cp16(base + 4u * VH_O + so, vph + (size_t)row * (SEQ / 2) + kn * 32 + wq);
                cp16(base + 4u * VL_O + so, vpl + (size_t)row * (SEQ / 2) + kn * 32 + wq);
            }
            CP_COMMIT();
        }
        uint32_t kvb = sb + 4u * (FKV0 + cur * KVBUF);
        uint32_t aKh = kvb + 4u * KH_O + oBf;
        uint32_t aKl = kvb + 4u * KL_O + oBf;
        uint32_t aVh = kvb + 4u * VH_O + oBf;
        uint32_t aVl = kvb + 4u * VL_O + oBf;

        float s[2][8][4];
#pragma unroll
        for (int mt = 0; mt < 2; mt++)
#pragma unroll
            for (int nt = 0; nt < 8; nt++)
#pragma unroll
                for (int e = 0; e < 4; e++) s[mt][nt][e] = 0.f;
#pragma unroll
        for (int ks = 0; ks < 4; ks++) {
            uint32_t qh[2][4], ql[2][4];
            ldsm_x4(qh[0], aQh + ks * 32);
            ldsm_x4(ql[0], aQl + ks * 32);
            ldsm_x4(qh[1], aQh + 16 * FSTR * 4 + ks * 32);
            ldsm_x4(ql[1], aQl + 16 * FSTR * 4 + ks * 32);
#pragma unroll
            for (int np = 0; np < 4; np++) {
                uint32_t kh4[4], kl4[4];
                ldsm_x4(kh4, aKh + np * (16 * FSTR * 4) + ks * 32);
                ldsm_x4(kl4, aKl + np * (16 * FSTR * 4) + ks * 32);
                mma3(s[0][2*np],   qh[0], ql[0], kh4[0], kh4[1], kl4[0], kl4[1]);
                mma3(s[0][2*np+1], qh[0], ql[0], kh4[2], kh4[3], kl4[2], kl4[3]);
                mma3(s[1][2*np],   qh[1], ql[1], kh4[0], kh4[1], kl4[0], kl4[1]);
                mma3(s[1][2*np+1], qh[1], ql[1], kh4[2], kh4[3], kl4[2], kl4[3]);
            }
        }

#pragma unroll
        for (int mt = 0; mt < 2; mt++) {
            float rm0 = -1e30f, rm1 = -1e30f;
#pragma unroll
            for (int nt = 0; nt < 8; nt++) {
                rm0 = fmaxf(rm0, fmaxf(s[mt][nt][0], s[mt][nt][1]));
                rm1 = fmaxf(rm1, fmaxf(s[mt][nt][2], s[mt][nt][3]));
            }
            rm0 = fmaxf(rm0, __shfl_xor_sync(0xffffffffu, rm0, 1));
            rm0 = fmaxf(rm0, __shfl_xor_sync(0xffffffffu, rm0, 2));
            rm1 = fmaxf(rm1, __shfl_xor_sync(0xffffffffu, rm1, 1));
            rm1 = fmaxf(rm1, __shfl_xor_sync(0xffffffffu, rm1, 2));
            float mn0 = fmaxf(m[mt][0], rm0), mn1 = fmaxf(m[mt][1], rm1);
            float corr0 = ex2f(m[mt][0] - mn0), corr1 = ex2f(m[mt][1] - mn1);
            m[mt][0] = mn0; m[mt][1] = mn1;
            float rs0 = 0.f, rs1 = 0.f;
#pragma unroll
            for (int nt = 0; nt < 8; nt++) {
                s[mt][nt][0] = ex2f(s[mt][nt][0] - mn0); rs0 += s[mt][nt][0];
                s[mt][nt][1] = ex2f(s[mt][nt][1] - mn0); rs0 += s[mt][nt][1];
                s[mt][nt][2] = ex2f(s[mt][nt][2] - mn1); rs1 += s[mt][nt][2];
                s[mt][nt][3] = ex2f(s[mt][nt][3] - mn1); rs1 += s[mt][nt][3];
            }
            rs0 += __shfl_xor_sync(0xffffffffu, rs0, 1);
            rs0 += __shfl_xor_sync(0xffffffffu, rs0, 2);
            rs1 += __shfl_xor_sync(0xffffffffu, rs1, 1);
            rs1 += __shfl_xor_sync(0xffffffffu, rs1, 2);
            l[mt][0] = l[mt][0] * corr0 + rs0;
            l[mt][1] = l[mt][1] * corr1 + rs1;
#pragma unroll
            for (int nt = 0; nt < 8; nt++) {
                ctx[mt][nt][0] *= corr0; ctx[mt][nt][1] *= corr0;
                ctx[mt][nt][2] *= corr1; ctx[mt][nt][3] *= corr1;
            }
        }

#pragma unroll
        for (int ks = 0; ks < 4; ks++) {
            uint32_t ph[2][4], pl[2][4];
#pragma unroll
            for (int mt = 0; mt < 2; mt++) {
                split2(s[mt][2*ks][0],   s[mt][2*ks][1],   ph[mt][0], pl[mt][0]);
                split2(s[mt][2*ks][2],   s[mt][2*ks][3],   ph[mt][1], pl[mt][1]);
                split2(s[mt][2*ks+1][0], s[mt][2*ks+1][1], ph[mt][2], pl[mt][2]);
                split2(s[mt][2*ks+1][2], s[mt][2*ks+1][3], ph[mt][3], pl[mt][3]);
            }
#pragma unroll
            for (int np = 0; np < 4; np++) {
                uint32_t vh4[4], vl4[4];
                ldsm_x4(vh4, aVh + np * (16 * FSTR * 4) + ks * 32);
                ldsm_x4(vl4, aVl + np * (16 * FSTR * 4) + ks * 32);
                mma3(ctx[0][2*np],   ph[0], pl[0], vh4[0], vh4[1], vl4[0], vl4[1]);
                mma3(ctx[0][2*np+1], ph[0], pl[0], vh4[2], vh4[3], vl4[2], vl4[3]);
                mma3(ctx[1][2*np],   ph[1], pl[1], vh4[0], vh4[1], vl4[0], vl4[1]);
                mma3(ctx[1][2*np+1], ph[1], pl[1], vh4[2], vh4[3], vl4[2], vl4[3]);
            }
        }
    }

    int g = lane >> 2, tig = lane & 3;
#pragma unroll
    for (int mt = 0; mt < 2; mt++) {
        float invl0 = 1.0f / l[mt][0], invl1 = 1.0f / l[mt][1];
        int r0 = q0 + rb + mt * 16 + g;
#pragma unroll
        for (int nt = 0; nt < 8; nt++) {
            int col = h * HD + nt * 8 + 2 * tig;
            *(float2*)(g_ctx + ((size_t)b * SEQ + r0) * DM + col) =
                make_float2(ctx[mt][nt][0] * invl0, ctx[mt][nt][1] * invl0);
            *(float2*)(g_ctx + ((size_t)b * SEQ + r0 + 8) * DM + col) =
                make_float2(ctx[mt][nt][2] * invl1, ctx[mt][nt][3] * invl1);
        }
    }
}

// ============================================================
// 4) out = ctx @ out_w^T + out_b (champion)
// ============================================================
__global__ __launch_bounds__(128) void out_mma_kernel(const float* __restrict__ wgt,
                                                      const float* __restrict__ bias,
                                                      float* __restrict__ out) {
    extern __shared__ uint32_t qsm[];
    int t = threadIdx.x, w = t >> 5, lane = t & 31;
    int g = lane >> 2, tig = lane & 3;
    int row0 = blockIdx.x * 128;
    int col0 = blockIdx.y * 64;
    const float* Ap = g_ctx + (size_t)row0 * DM;
    const float* Bp = wgt   + (size_t)col0 * DM;

    uint32_t sb = smem_to_u32(qsm);
    uint32_t oA = offA(w * 32, GSTR, lane);
    uint32_t oBf = offB(GSTR, lane);

    float acc[2][8][4];
#pragma unroll
    for (int mt = 0; mt < 2; mt++)
#pragma unroll
        for (int nt = 0; nt < 8; nt++)
#pragma unroll
            for (int e = 0; e < 4; e++) acc[mt][nt][e] = 0.f;

    float4 aR[8], bR[4];
#pragma unroll
    for (int j = 0; j < 8; j++) {
        int idx = j * 128 + t;
        int row = idx >> 3, kg = idx & 7;
        aR[j] = *(const float4*)(Ap + (size_t)row * DM + kg * 4);
    }
#pragma unroll
    for (int j = 0; j < 4; j++) {
        int idx = j * 128 + t;
        int n = idx >> 3, kg = idx & 7;
        bR[j] = *(const float4*)(Bp + (size_t)n * DM + kg * 4);
    }

    const int NC = DM / 32;
    for (int c = 0; c < NC; c++) {
        int cur = c & 1;
        uint32_t* Ah = qsm + cur * QBUF + QA_H;
        uint32_t* Al = qsm + cur * QBUF + QA_L;
        uint32_t* Bh = qsm + cur * QBUF + QB_H;
        uint32_t* Bl = qsm + cur * QBUF + QB_L;
#pragma unroll
        for (int j = 0; j < 8; j++) {
            int idx = j * 128 + t;
            int row = idx >> 3, kg = idx & 7;
            uint32_t h2[2], l2[2]; split4(aR[j], h2, l2);
            Ah[row * GSTR + kg * 2] = h2[0]; Ah[row * GSTR + kg * 2 + 1] = h2[1];
            Al[row * GSTR + kg * 2] = l2[0]; Al[row * GSTR + kg * 2 + 1] = l2[1];
        }
#pragma unroll
        for (int j = 0; j < 4; j++) {
            int idx = j * 128 + t;
            int n = idx >> 3, kg = idx & 7;
            uint32_t h2[2], l2[2]; split4(bR[j], h2, l2);
            Bh[n * GSTR + kg * 2] = h2[0]; Bh[n * GSTR + kg * 2 + 1] = h2[1];
            Bl[n * GSTR + kg * 2] = l2[0]; Bl[n * GSTR + kg * 2 + 1] = l2[1];
        }
        __syncthreads();
        if (c + 1 < NC) {
            int k0 = (c + 1) * 32;
#pragma unroll
            for (int j = 0; j < 8; j++) {
                int idx = j * 128 + t;
                int row = idx >> 3, kg = idx & 7;
                aR[j] = *(const float4*)(Ap + (size_t)row * DM + k0 + kg * 4);
            }
#pragma unroll
            for (int j = 0; j < 4; j++) {
                int idx = j * 128 + t;
                int n = idx >> 3, kg = idx & 7;
                bR[j] = *(const float4*)(Bp + (size_t)n * DM + k0 + kg * 4);
            }
        }
        uint32_t aAh = sb + 4u * (cur * QBUF + QA_H) + oA;
        uint32_t aAl = sb + 4u * (cur * QBUF + QA_L) + oA;
        uint32_t aBh = sb + 4u * (cur * QBUF + QB_H) + oBf;
        uint32_t aBl = sb + 4u * (cur * QBUF + QB_L) + oBf;
#pragma unroll
        for (int ks = 0; ks < 2; ks++) {
            uint32_t ah[2][4], al[2][4];
            ldsm_x4(ah[0], aAh + ks * 32);
            ldsm_x4(ah[1], aAh + 16 * GSTR * 4 + ks * 32);
            ldsm_x4(al[0], aAl + ks * 32);
            ldsm_x4(al[1], aAl + 16 * GSTR * 4 + ks * 32);
#pragma unroll
            for (int np = 0; np < 4; np++) {
                uint32_t kh4[4], kl4[4];
                ldsm_x4(kh4, aBh + np * (16 * GSTR * 4) + ks * 32);
                ldsm_x4(kl4, aBl + np * (16 * GSTR * 4) + ks * 32);
                mma3(acc[0][2*np],   ah[0], al[0], kh4[0], kh4[1], kl4[0], kl4[1]);
                mma3(acc[0][2*np+1], ah[0], al[0], kh4[2], kh4[3], kl4[2], kl4[3]);
                mma3(acc[1][2*np],   ah[1], al[1], kh4[0], kh4[1], kl4[0], kl4[1]);
                mma3(acc[1][2*np+1], ah[1], al[1], kh4[2], kh4[3], kl4[2], kl4[3]);
            }
        }
    }
#pragma unroll
    for (int mt = 0; mt < 2; mt++)
#pragma unroll
        for (int nt = 0; nt < 8; nt++) {
            int col = col0 + nt * 8 + 2 * tig;
            size_t r0 = row0 + w * 32 + mt * 16 + g;
            float2 bi = *(const float2*)(bias + col);
            *(float2*)(out + r0 * DM + col) =
                make_float2(acc[mt][nt][0] + bi.x, acc[mt][nt][1] + bi.y);
            *(float2*)(out + (r0 + 8) * DM + col) =
                make_float2(acc[mt][nt][2] + bi.x, acc[mt][nt][3] + bi.y);
        }
}

// ============================================================
extern "C" void kernel_launch(void* const* d_in, const int* in_sizes, int n_in,
                              void* d_out, int out_size) {
    (void)in_sizes; (void)n_in; (void)out_size;
    const float* q    = (const float*)d_in[0];
    const float* k    = (const float*)d_in[1];
    const float* v    = (const float*)d_in[2];
    const float* mask = (const float*)d_in[3];
    const float* ow   = (const float*)d_in[4];
    const float* ob   = (const float*)d_in[5];
    float* out = (float*)d_out;

    cudaFuncSetAttribute(flash_kernel, cudaFuncAttributeMaxDynamicSharedMemorySize,
                         FLASH_SMEM_BYTES);
    cudaFuncSetAttribute(qt_mma_kernel, cudaFuncAttributeMaxDynamicSharedMemorySize,
                         QT_SMEM_BYTES);
    cudaFuncSetAttribute(out_mma_kernel, cudaFuncAttributeMaxDynamicSharedMemorySize,
                         QT_SMEM_BYTES);

    rope_v_kernel<<<dim3(SEQ / 32, BH), 256>>>(q, k, v);
    qt_mma_kernel<<<dim3(SEQ / 128, BH), 128, QT_SMEM_BYTES>>>(mask);
    flash_kernel<<<dim3(SEQ / 128, BH), 128, FLASH_SMEM_BYTES>>>();
    out_mma_kernel<<<dim3(NB * SEQ / 128, DM / 64), 128, QT_SMEM_BYTES>>>(ow, ob, out);
}